// round 5
// baseline (speedup 1.0000x reference)
#include <cuda_runtime.h>
#include <cuda_bf16.h>
#include <cstdint>

// Problem shape
#define NB  16
#define NL  2048
#define NH  768
#define ND  64
#define CK  128
#define NCH (NL/CK)       // 16
#define HT  128
#define NHT (NH/HT)       // 6
#define DH  (ND*NH)       // 49152

typedef unsigned int u32;

// Scratch (static device arrays — no allocation)
__device__ float g_E [NB*NL*ND];       // gathered embeddings (fp32, for k_scores)
__device__ float g_Fp[NB*NL*ND];       // (l+1)*(E@w)         (fp32, for k_scores)
__device__ float g_M [NB*NCH*DH];      // chunk outer products M[d][h] (fp32)

// pre-split bf16 hi/lo pairs (producer-side splits; same bytes as fp32)
__device__ __nv_bfloat16 cEh[NB*NL*ND],      cEl[NB*NL*ND];       // E  [j][d]
__device__ __nv_bfloat16 cFh[NB*NL*ND],      cFl[NB*NL*ND];       // Fp [i][d]
__device__ __nv_bfloat16 cSh[NB*NCH*CK*CK],  cSl[NB*NCH*CK*CK];   // S  [j][i] masked
__device__ __nv_bfloat16 cMh[NB*NCH*DH],     cMl[NB*NCH*DH];      // Mexcl [d][h]

// ---------------------------------------------------------------------------
// helpers
// ---------------------------------------------------------------------------
__device__ __forceinline__ u32 smem_u32(const void* p) {
    u32 a;
    asm("{ .reg .u64 t; cvta.to.shared.u64 t, %1; cvt.u32.u64 %0, t; }" : "=r"(a) : "l"(p));
    return a;
}
__device__ __forceinline__ u32 packbf(__nv_bfloat16 a, __nv_bfloat16 b) {
    __nv_bfloat162 t(a, b);
    return *reinterpret_cast<u32*>(&t);
}
__device__ __forceinline__ void splitpack(float a, float b, u32& hi, u32& lo) {
    __nv_bfloat16 ah = __float2bfloat16(a);
    __nv_bfloat16 bh = __float2bfloat16(b);
    __nv_bfloat16 al = __float2bfloat16(a - __bfloat162float(ah));
    __nv_bfloat16 bl = __float2bfloat16(b - __bfloat162float(bh));
    hi = packbf(ah, bh);
    lo = packbf(al, bl);
}

__device__ __forceinline__ void ldsm4(u32* r, u32 addr) {
    asm volatile("ldmatrix.sync.aligned.m8n8.x4.shared.b16 {%0,%1,%2,%3}, [%4];"
        : "=r"(r[0]), "=r"(r[1]), "=r"(r[2]), "=r"(r[3]) : "r"(addr));
}
__device__ __forceinline__ void ldsm4t(u32* r, u32 addr) {
    asm volatile("ldmatrix.sync.aligned.m8n8.x4.trans.shared.b16 {%0,%1,%2,%3}, [%4];"
        : "=r"(r[0]), "=r"(r[1]), "=r"(r[2]), "=r"(r[3]) : "r"(addr));
}
__device__ __forceinline__ void mma16816(float* d, const u32* a, const u32* b) {
    asm volatile("mma.sync.aligned.m16n8k16.row.col.f32.bf16.bf16.f32 "
        "{%0,%1,%2,%3}, {%4,%5,%6,%7}, {%8,%9}, {%0,%1,%2,%3};"
        : "+f"(d[0]), "+f"(d[1]), "+f"(d[2]), "+f"(d[3])
        : "r"(a[0]), "r"(a[1]), "r"(a[2]), "r"(a[3]), "r"(b[0]), "r"(b[1]));
}

// ---------------------------------------------------------------------------
// smem tile loaders
// A-tile: [ROWS][64 k] bf16, 128B rows; chunk c (16B): off = r*128 + ((c^(r&7))<<4)
// B-tile: [64][128 n]  bf16, 256B rows; chunk c:       off = r*256 + ((c^(r&7))<<4)
// ---------------------------------------------------------------------------

// pure copy from pre-split hi/lo arrays (A layout)
template<int ROWS>
__device__ __forceinline__ void loadAcp(char* sm, int offH, int offL,
                                        const __nv_bfloat16* __restrict__ gh,
                                        const __nv_bfloat16* __restrict__ gl,
                                        int gs, int tid)
{
    #pragma unroll
    for (int it = 0; it < ROWS * 8 / 256; it++) {
        int idx = tid + it * 256;
        int r = idx >> 3, c = idx & 7;
        uint4 vh = *(const uint4*)(gh + (size_t)r * gs + c * 8);
        uint4 vl = *(const uint4*)(gl + (size_t)r * gs + c * 8);
        int off = r * 128 + ((c ^ (r & 7)) << 4);
        *(uint4*)(sm + offH + off) = vh;
        *(uint4*)(sm + offL + off) = vl;
    }
}
// pure copy, B layout (64 x 128)
__device__ __forceinline__ void loadBcp(char* sm, int offH, int offL,
                                        const __nv_bfloat16* __restrict__ gh,
                                        const __nv_bfloat16* __restrict__ gl,
                                        int gs, int tid)
{
    #pragma unroll
    for (int it = 0; it < 4; it++) {
        int idx = tid + it * 256;
        int r = idx >> 4, c = idx & 15;
        uint4 vh = *(const uint4*)(gh + (size_t)r * gs + c * 8);
        uint4 vl = *(const uint4*)(gl + (size_t)r * gs + c * 8);
        int off = r * 256 + ((c ^ (r & 7)) << 4);
        *(uint4*)(sm + offH + off) = vh;
        *(uint4*)(sm + offL + off) = vl;
    }
}
// convert-on-load from fp32 (B layout) — X only
__device__ __forceinline__ void loadBcv(char* sm, int offH, int offL,
                                        const float* __restrict__ g, int gs, int tid)
{
    #pragma unroll
    for (int it = 0; it < 4; it++) {
        int idx = tid + it * 256;
        int r = idx >> 4, c = idx & 15;
        const float* p = g + (size_t)r * gs + c * 8;
        float4 v0 = *(const float4*)p;
        float4 v1 = *(const float4*)(p + 4);
        u32 h0,l0,h1,l1,h2,l2,h3,l3;
        splitpack(v0.x, v0.y, h0, l0);
        splitpack(v0.z, v0.w, h1, l1);
        splitpack(v1.x, v1.y, h2, l2);
        splitpack(v1.z, v1.w, h3, l3);
        int off = r * 256 + ((c ^ (r & 7)) << 4);
        *(uint4*)(sm + offH + off) = make_uint4(h0, h1, h2, h3);
        *(uint4*)(sm + offL + off) = make_uint4(l0, l1, l2, l3);
    }
}

// ---------------------------------------------------------------------------
// K0: embedding gather + Fp = (l+1) * E @ w ; emits fp32 + bf16 hi/lo pairs
// ---------------------------------------------------------------------------
__global__ void k_embed(const void* __restrict__ xraw,
                        const float* __restrict__ ae,
                        const float* __restrict__ w)
{
    __shared__ float sW[ND][ND];
    __shared__ float sE[4][ND];

    int tid = threadIdx.x;

    // Detect index dtype: int64 (odd 32-bit words all zero) vs int32.
    const int* xi = (const int*)xraw;
    int oddw = xi[((tid & 63) << 1) + 1];
    int is64 = __syncthreads_and(oddw == 0);

    for (int i = tid; i < ND * ND; i += 256)
        ((float*)sW)[i] = w[i];

    int q = tid >> 6;
    int d = tid & 63;
    int t = blockIdx.x * 4 + q;
    int l = t & (NL - 1);

    long long v;
    if (is64) v = ((const long long*)xraw)[t];
    else      v = (long long)xi[t];

    float e = ae[v * ND + d];
    sE[q][d] = e;
    size_t td = (size_t)t * ND + d;
    g_E[td] = e;
    {
        __nv_bfloat16 eh = __float2bfloat16(e);
        cEh[td] = eh;
        cEl[td] = __float2bfloat16(e - __bfloat162float(eh));
    }
    __syncthreads();

    float acc = 0.f;
    #pragma unroll
    for (int k = 0; k < ND; k++)
        acc += sE[q][k] * sW[k][d];

    float fp = (float)(l + 1) * acc;
    g_Fp[td] = fp;
    {
        __nv_bfloat16 fh = __float2bfloat16(fp);
        cFh[td] = fh;
        cFl[td] = __float2bfloat16(fp - __bfloat162float(fh));
    }
}

// ---------------------------------------------------------------------------
// K1b: intra-chunk scores S[j][i] = E[j].Fp[i], zero for i >= j.
// grid (2, NCH, NB): CTA tile 64(j) x 128(i), 256 thr, micro 4x8.
// Emits masked bf16 hi/lo pairs directly.
// ---------------------------------------------------------------------------
__global__ void k_scores()
{
    __shared__ float sEt[32][64];
    __shared__ float sFt[32][CK];

    int tid = threadIdx.x;
    int jh = blockIdx.x, c = blockIdx.y, b = blockIdx.z;
    int j0 = jh * 64;

    const float* Eb  = g_E  + ((size_t)b * NL + c * CK + j0) * ND;
    const float* Fpb = g_Fp + ((size_t)b * NL + c * CK) * ND;

    int tj = tid & 15;      // j-quad
    int ti = tid >> 4;      // i-oct

    float acc[4][8];
    #pragma unroll
    for (int r = 0; r < 4; r++)
        #pragma unroll
        for (int s = 0; s < 8; s++) acc[r][s] = 0.f;

    for (int dt = 0; dt < ND; dt += 32) {
        int f4 = tid & 7, r0 = tid >> 3;
        #pragma unroll
        for (int rep = 0; rep < 2; rep++) {      // E: 64 rows
            int row = r0 + rep * 32;
            float4 v = *(const float4*)(Eb + (size_t)row * ND + dt + f4 * 4);
            sEt[f4*4+0][row] = v.x; sEt[f4*4+1][row] = v.y;
            sEt[f4*4+2][row] = v.z; sEt[f4*4+3][row] = v.w;
        }
        #pragma unroll
        for (int rep = 0; rep < 4; rep++) {      // Fp: 128 rows
            int row = r0 + rep * 32;
            float4 u = *(const float4*)(Fpb + (size_t)row * ND + dt + f4 * 4);
            sFt[f4*4+0][row] = u.x; sFt[f4*4+1][row] = u.y;
            sFt[f4*4+2][row] = u.z; sFt[f4*4+3][row] = u.w;
        }
        __syncthreads();

        #pragma unroll 8
        for (int kk = 0; kk < 32; kk++) {
            float4 a0 = *(const float4*)&sEt[kk][tj*4];
            float4 b0 = *(const float4*)&sFt[kk][ti*8];
            float4 b1 = *(const float4*)&sFt[kk][ti*8 + 4];
            float av[4] = {a0.x,a0.y,a0.z,a0.w};
            float bv[8] = {b0.x,b0.y,b0.z,b0.w,b1.x,b1.y,b1.z,b1.w};
            #pragma unroll
            for (int r = 0; r < 4; r++)
                #pragma unroll
                for (int s = 0; s < 8; s++)
                    acc[r][s] += av[r] * bv[s];
        }
        __syncthreads();
    }

    size_t Sb = (size_t)(b * NCH + c) * CK * CK;
    #pragma unroll
    for (int r = 0; r < 4; r++) {
        int j = j0 + tj * 4 + r;
        size_t row = Sb + (size_t)j * CK + ti * 8;
        u32 h[4], l[4];
        #pragma unroll
        for (int p = 0; p < 4; p++) {
            float a  = (ti*8 + 2*p     < j) ? acc[r][2*p]     : 0.f;
            float bb = (ti*8 + 2*p + 1 < j) ? acc[r][2*p + 1] : 0.f;
            splitpack(a, bb, h[p], l[p]);
        }
        *(uint4*)&cSh[row] = make_uint4(h[0], h[1], h[2], h[3]);
        *(uint4*)&cSl[row] = make_uint4(l[0], l[1], l[2], l[3]);
    }
}

// ---------------------------------------------------------------------------
// K1a (mma): M[b][c][d][h] = sum_i Fp[i][d] * X[i][h]  (fp32 out)
// A = Fp (pre-split pure copy), B = X (convert). CTA 64x128, warps 2x4.
// ---------------------------------------------------------------------------
#define KO_AH 0
#define KO_AL 8192
#define KO_BH 16384
#define KO_BL 32768
#define KO_TOT 49152

__global__ void __launch_bounds__(256, 1) k_outer_mma(const float* __restrict__ bx)
{
    extern __shared__ char sm[];
    u32 smb = smem_u32(sm);
    int tid = threadIdx.x, wid = tid >> 5, ln = tid & 31;
    int ht = blockIdx.x, c = blockIdx.y, b = blockIdx.z;
    int h0 = ht * HT;
    int mw = (wid >> 2) * 32;
    int nw = (wid & 3) * 32;

    const __nv_bfloat16* Fh = cFh + ((size_t)b * NL + c * CK) * ND;
    const __nv_bfloat16* Fl = cFl + ((size_t)b * NL + c * CK) * ND;
    const float* Xg = bx + ((size_t)b * NL + c * CK) * NH + h0;

    float acc[2][4][4];
    #pragma unroll
    for (int i = 0; i < 2; i++)
        #pragma unroll
        for (int j = 0; j < 4; j++)
            #pragma unroll
            for (int k = 0; k < 4; k++) acc[i][j][k] = 0.f;

    for (int slab = 0; slab < 2; slab++) {
        loadAcp<64>(sm, KO_AH, KO_AL, Fh + (size_t)slab * 64 * ND,
                    Fl + (size_t)slab * 64 * ND, ND, tid);
        loadBcv(sm, KO_BH, KO_BL, Xg + (size_t)slab * 64 * NH, NH, tid);
        __syncthreads();

        #pragma unroll
        for (int ks = 0; ks < 4; ks++) {
            u32 ah[2][4], al[2][4], bh[2][4], bl[2][4];
            int q = ln >> 3;
            #pragma unroll
            for (int mt = 0; mt < 2; mt++) {   // A trans: rows=k(i), cols=m(d)
                int r = ks * 16 + (q >> 1) * 8 + (ln & 7);
                int mc = (mw + mt * 16 + (q & 1) * 8) >> 3;
                u32 off = r * 128 + ((mc ^ (r & 7)) << 4);
                ldsm4t(ah[mt], smb + KO_AH + off);
                ldsm4t(al[mt], smb + KO_AL + off);
            }
            #pragma unroll
            for (int nt2 = 0; nt2 < 2; nt2++) { // B trans: rows=k(i), cols=n(h)
                int r = ks * 16 + (q & 1) * 8 + (ln & 7);
                int nc = (nw + nt2 * 16 + (q >> 1) * 8) >> 3;
                u32 off = r * 256 + ((nc ^ (r & 7)) << 4);
                ldsm4t(bh[nt2], smb + KO_BH + off);
                ldsm4t(bl[nt2], smb + KO_BL + off);
            }
            #pragma unroll
            for (int mt = 0; mt < 2; mt++)
                #pragma unroll
                for (int nt2 = 0; nt2 < 2; nt2++) {
                    mma16816(acc[mt][nt2*2],   ah[mt], &bh[nt2][0]);
                    mma16816(acc[mt][nt2*2+1], ah[mt], &bh[nt2][2]);
                    mma16816(acc[mt][nt2*2],   ah[mt], &bl[nt2][0]);
                    mma16816(acc[mt][nt2*2+1], ah[mt], &bl[nt2][2]);
                    mma16816(acc[mt][nt2*2],   al[mt], &bh[nt2][0]);
                    mma16816(acc[mt][nt2*2+1], al[mt], &bh[nt2][2]);
                }
        }
        __syncthreads();
    }

    float* Mo = g_M + (size_t)(b * NCH + c) * DH;
    #pragma unroll
    for (int mt = 0; mt < 2; mt++)
        #pragma unroll
        for (int half = 0; half < 2; half++) {
            int d = mw + mt * 16 + (ln >> 2) + half * 8;
            #pragma unroll
            for (int nt = 0; nt < 4; nt++) {
                int h = h0 + nw + nt * 8 + (ln & 3) * 2;
                *(float2*)(Mo + (size_t)d * NH + h) =
                    make_float2(acc[mt][nt][half*2], acc[mt][nt][half*2 + 1]);
            }
        }
}

// ---------------------------------------------------------------------------
// K2: exclusive prefix over chunks; reads g_M fp32, emits bf16 hi/lo pairs.
// float4-vectorized: one thread per 4 consecutive (d,h) elems.
// ---------------------------------------------------------------------------
__global__ void k_prefix()
{
    int idx = blockIdx.x * 256 + threadIdx.x;      // < NB*DH/4
    int b = idx / (DH / 4);
    int q = idx - b * (DH / 4);
    size_t p = (size_t)(b * NCH) * DH + (size_t)q * 4;
    float4 run = make_float4(0.f, 0.f, 0.f, 0.f);
    #pragma unroll
    for (int c = 0; c < NCH; c++) {
        float4 v = *(const float4*)&g_M[p];
        u32 h0, l0, h1, l1;
        splitpack(run.x, run.y, h0, l0);
        splitpack(run.z, run.w, h1, l1);
        *(uint2*)&cMh[p] = make_uint2(h0, h1);
        *(uint2*)&cMl[p] = make_uint2(l0, l1);
        run.x += v.x; run.y += v.y; run.z += v.z; run.w += v.w;
        p += DH;
    }
}

// ---------------------------------------------------------------------------
// K3 (mma): out[j][h] = X[j][h] + (1/(j+1)) * ( E@M + tril(S,-1)@X )
// slab0: A=E(copy), B=M(copy); slab1,2: A=S(copy), B=X(convert).
// CTA 128x128, warps 2x4, warp tile 64x32.
// ---------------------------------------------------------------------------
#define KF_AH 0
#define KF_AL 16384
#define KF_BH 32768
#define KF_BL 49152
#define KF_TOT 65536

__global__ void __launch_bounds__(256, 1) k_final_mma(const float* __restrict__ bx,
                                                      float* __restrict__ out)
{
    extern __shared__ char sm[];
    u32 smb = smem_u32(sm);
    int tid = threadIdx.x, wid = tid >> 5, ln = tid & 31;
    int ht = blockIdx.x, c = blockIdx.y, b = blockIdx.z;
    int h0 = ht * HT;
    int mw = (wid >> 2) * 64;
    int nw = (wid & 3) * 32;

    size_t Eb = ((size_t)b * NL + c * CK) * ND;
    size_t Sb = (size_t)(b * NCH + c) * CK * CK;
    size_t Mb = (size_t)(b * NCH + c) * DH + h0;
    const float* Xg = bx + ((size_t)b * NL + c * CK) * NH + h0;

    float acc[4][4][4];
    #pragma unroll
    for (int i = 0; i < 4; i++)
        #pragma unroll
        for (int j = 0; j < 4; j++)
            #pragma unroll
            for (int k = 0; k < 4; k++) acc[i][j][k] = 0.f;

    for (int slab = 0; slab < 3; slab++) {
        if (slab == 0) {
            loadAcp<128>(sm, KF_AH, KF_AL, cEh + Eb, cEl + Eb, ND, tid);
            loadBcp(sm, KF_BH, KF_BL, cMh + Mb, cMl + Mb, NH, tid);
        } else {
            size_t so = Sb + (size_t)(slab - 1) * 64;
            loadAcp<128>(sm, KF_AH, KF_AL, cSh + so, cSl + so, CK, tid);
            loadBcv(sm, KF_BH, KF_BL, Xg + (size_t)(slab - 1) * 64 * NH, NH, tid);
        }
        __syncthreads();

        #pragma unroll
        for (int ks = 0; ks < 4; ks++) {
            u32 ah[4][4], al[4][4], bh[2][4], bl[2][4];
            #pragma unroll
            for (int mt = 0; mt < 4; mt++) {   // A non-trans: rows=m(j), cols=k
                int row = mw + mt * 16 + (ln & 15);
                int kc = ks * 2 + (ln >> 4);
                u32 off = row * 128 + ((kc ^ (row & 7)) << 4);
                ldsm4(ah[mt], smb + KF_AH + off);
                ldsm4(al[mt], smb + KF_AL + off);
            }
            int q = ln >> 3;
            #pragma unroll
            for (int nt2 = 0; nt2 < 2; nt2++) { // B trans: rows=k, cols=n(h)
                int r = ks * 16 + (q & 1) * 8 + (ln & 7);
                int nc = (nw + nt2 * 16 + (q >> 1) * 8) >> 3;
                u32 off = r * 256 + ((nc ^ (r & 7)) << 4);
                ldsm4t(bh[nt2], smb + KF_BH + off);
                ldsm4t(bl[nt2], smb + KF_BL + off);
            }
            #pragma unroll
            for (int mt = 0; mt < 4; mt++)
                #pragma unroll
                for (int nt2 = 0; nt2 < 2; nt2++) {
                    mma16816(acc[mt][nt2*2],   ah[mt], &bh[nt2][0]);
                    mma16816(acc[mt][nt2*2+1], ah[mt], &bh[nt2][2]);
                    mma16816(acc[mt][nt2*2],   ah[mt], &bl[nt2][0]);
                    mma16816(acc[mt][nt2*2+1], ah[mt], &bl[nt2][2]);
                    mma16816(acc[mt][nt2*2],   al[mt], &bh[nt2][0]);
                    mma16816(acc[mt][nt2*2+1], al[mt], &bh[nt2][2]);
                }
        }
        __syncthreads();
    }

    // Epilogue: out = x + (1/(j+1)) * acc
    #pragma unroll
    for (int mt = 0; mt < 4; mt++)
        #pragma unroll
        for (int half = 0; half < 2; half++) {
            int jl = mw + mt * 16 + (ln >> 2) + half * 8;
            float rj = 1.f / (float)(c * CK + jl + 1);
            size_t base = ((size_t)b * NL + c * CK + jl) * NH + h0 + nw + (ln & 3) * 2;
            #pragma unroll
            for (int nt = 0; nt < 4; nt++) {
                float2 x = *(const float2*)(bx + base + nt * 8);
                *(float2*)(out + base + nt * 8) =
                    make_float2(x.x + rj * acc[mt][nt][half*2],
                                x.y + rj * acc[mt][nt][half*2 + 1]);
            }
        }
}

// ---------------------------------------------------------------------------
extern "C" void kernel_launch(void* const* d_in, const int* in_sizes, int n_in,
                              void* d_out, int out_size)
{
    const float* bx = (const float*)d_in[0];   // bert_x [B,L,H] f32
    const void*  x  = d_in[1];                 // x      [B,L]   int32/int64 (auto)
    const float* ae = (const float*)d_in[2];   // ae     [V,D]   f32
    const float* w  = (const float*)d_in[3];   // w      [D,D]   f32
    float* out = (float*)d_out;

    (void)in_sizes; (void)n_in; (void)out_size;

    cudaFuncSetAttribute(k_outer_mma, cudaFuncAttributeMaxDynamicSharedMemorySize, KO_TOT);
    cudaFuncSetAttribute(k_final_mma, cudaFuncAttributeMaxDynamicSharedMemorySize, KF_TOT);

    k_embed    <<<NB * NL / 4, 256>>>(x, ae, w);
    k_scores   <<<dim3(2, NCH, NB), 256>>>();
    k_outer_mma<<<dim3(NHT, NCH, NB), 256, KO_TOT>>>(bx);
    k_prefix   <<<NB * DH / 1024, 256>>>();
    k_final_mma<<<dim3(NHT, NCH, NB), 256, KF_TOT>>>(bx, out);
}

// round 6
// speedup vs baseline: 1.4329x; 1.4329x over previous
#include <cuda_runtime.h>
#include <cuda_bf16.h>
#include <cstdint>

// Problem shape
#define NB  16
#define NL  2048
#define NH  768
#define ND  64
#define CK  128
#define NCH (NL/CK)       // 16
#define HT  128
#define NHT (NH/HT)       // 6
#define DH  (ND*NH)       // 49152

typedef unsigned int u32;

// Scratch — every array is 4 B/elem; total 83.6 MB (same as round-4 winner)
__device__ u32   cEp[NB*NL*ND];        // E  packed (hi16|lo16)
__device__ u32   cFp[NB*NL*ND];        // Fp packed
__device__ u32   cSp[NB*NCH*CK*CK];    // S  packed, masked
__device__ float g_M[NB*NCH*DH];       // chunk outer products fp32 -> packed in place by k_prefix

// ---------------------------------------------------------------------------
// helpers
// ---------------------------------------------------------------------------
__device__ __forceinline__ u32 smem_u32(const void* p) {
    u32 a;
    asm("{ .reg .u64 t; cvta.to.shared.u64 t, %1; cvt.u32.u64 %0, t; }" : "=r"(a) : "l"(p));
    return a;
}
__device__ __forceinline__ u32 packbf(__nv_bfloat16 a, __nv_bfloat16 b) {
    __nv_bfloat162 t(a, b);
    return *reinterpret_cast<u32*>(&t);
}
// one fp32 -> packed (hi in low 16, lo in high 16)
__device__ __forceinline__ u32 packsplit(float v) {
    __nv_bfloat16 h = __float2bfloat16(v);
    __nv_bfloat16 l = __float2bfloat16(v - __bfloat162float(h));
    return packbf(h, l);
}
// packed -> fp32 reconstruct
__device__ __forceinline__ float rec(u32 p) {
    __nv_bfloat162 t = *reinterpret_cast<__nv_bfloat162*>(&p);
    return __bfloat162float(t.x) + __bfloat162float(t.y);
}
// split two fp32 into hi/lo bf16x2 words (X convert-on-load only)
__device__ __forceinline__ void splitpack(float a, float b, u32& hi, u32& lo) {
    __nv_bfloat16 ah = __float2bfloat16(a);
    __nv_bfloat16 bh = __float2bfloat16(b);
    __nv_bfloat16 al = __float2bfloat16(a - __bfloat162float(ah));
    __nv_bfloat16 bl = __float2bfloat16(b - __bfloat162float(bh));
    hi = packbf(ah, bh);
    lo = packbf(al, bl);
}

__device__ __forceinline__ void ldsm4(u32* r, u32 addr) {
    asm volatile("ldmatrix.sync.aligned.m8n8.x4.shared.b16 {%0,%1,%2,%3}, [%4];"
        : "=r"(r[0]), "=r"(r[1]), "=r"(r[2]), "=r"(r[3]) : "r"(addr));
}
__device__ __forceinline__ void ldsm4t(u32* r, u32 addr) {
    asm volatile("ldmatrix.sync.aligned.m8n8.x4.trans.shared.b16 {%0,%1,%2,%3}, [%4];"
        : "=r"(r[0]), "=r"(r[1]), "=r"(r[2]), "=r"(r[3]) : "r"(addr));
}
__device__ __forceinline__ void mma16816(float* d, const u32* a, const u32* b) {
    asm volatile("mma.sync.aligned.m16n8k16.row.col.f32.bf16.bf16.f32 "
        "{%0,%1,%2,%3}, {%4,%5,%6,%7}, {%8,%9}, {%0,%1,%2,%3};"
        : "+f"(d[0]), "+f"(d[1]), "+f"(d[2]), "+f"(d[3])
        : "r"(a[0]), "r"(a[1]), "r"(a[2]), "r"(a[3]), "r"(b[0]), "r"(b[1]));
}

// ---------------------------------------------------------------------------
// smem tile loaders (deinterleave packed hi/lo via PRMT)
// A-tile: [ROWS][64 k], 128B rows; chunk c: off = r*128 + ((c^(r&7))<<4)
// B-tile: [64][128 n],  256B rows; chunk c: off = r*256 + ((c^(r&7))<<4)
// ---------------------------------------------------------------------------
template<int ROWS>
__device__ __forceinline__ void loadAdi(char* sm, int offH, int offL,
                                        const u32* __restrict__ g, int gs, int tid)
{
    #pragma unroll
    for (int it = 0; it < ROWS * 8 / 256; it++) {
        int idx = tid + it * 256;
        int r = idx >> 3, c = idx & 7;
        const u32* p = g + (size_t)r * gs + c * 8;
        uint4 q0 = *(const uint4*)p;
        uint4 q1 = *(const uint4*)(p + 4);
        u32 h0 = __byte_perm(q0.x, q0.y, 0x5410), l0 = __byte_perm(q0.x, q0.y, 0x7632);
        u32 h1 = __byte_perm(q0.z, q0.w, 0x5410), l1 = __byte_perm(q0.z, q0.w, 0x7632);
        u32 h2 = __byte_perm(q1.x, q1.y, 0x5410), l2 = __byte_perm(q1.x, q1.y, 0x7632);
        u32 h3 = __byte_perm(q1.z, q1.w, 0x5410), l3 = __byte_perm(q1.z, q1.w, 0x7632);
        int off = r * 128 + ((c ^ (r & 7)) << 4);
        *(uint4*)(sm + offH + off) = make_uint4(h0, h1, h2, h3);
        *(uint4*)(sm + offL + off) = make_uint4(l0, l1, l2, l3);
    }
}
__device__ __forceinline__ void loadBdi(char* sm, int offH, int offL,
                                        const u32* __restrict__ g, int gs, int tid)
{
    #pragma unroll
    for (int it = 0; it < 4; it++) {
        int idx = tid + it * 256;
        int r = idx >> 4, c = idx & 15;
        const u32* p = g + (size_t)r * gs + c * 8;
        uint4 q0 = *(const uint4*)p;
        uint4 q1 = *(const uint4*)(p + 4);
        u32 h0 = __byte_perm(q0.x, q0.y, 0x5410), l0 = __byte_perm(q0.x, q0.y, 0x7632);
        u32 h1 = __byte_perm(q0.z, q0.w, 0x5410), l1 = __byte_perm(q0.z, q0.w, 0x7632);
        u32 h2 = __byte_perm(q1.x, q1.y, 0x5410), l2 = __byte_perm(q1.x, q1.y, 0x7632);
        u32 h3 = __byte_perm(q1.z, q1.w, 0x5410), l3 = __byte_perm(q1.z, q1.w, 0x7632);
        int off = r * 256 + ((c ^ (r & 7)) << 4);
        *(uint4*)(sm + offH + off) = make_uint4(h0, h1, h2, h3);
        *(uint4*)(sm + offL + off) = make_uint4(l0, l1, l2, l3);
    }
}
// convert-on-load from fp32 (B layout) — X only
__device__ __forceinline__ void loadBcv(char* sm, int offH, int offL,
                                        const float* __restrict__ g, int gs, int tid)
{
    #pragma unroll
    for (int it = 0; it < 4; it++) {
        int idx = tid + it * 256;
        int r = idx >> 4, c = idx & 15;
        const float* p = g + (size_t)r * gs + c * 8;
        float4 v0 = *(const float4*)p;
        float4 v1 = *(const float4*)(p + 4);
        u32 h0,l0,h1,l1,h2,l2,h3,l3;
        splitpack(v0.x, v0.y, h0, l0);
        splitpack(v0.z, v0.w, h1, l1);
        splitpack(v1.x, v1.y, h2, l2);
        splitpack(v1.z, v1.w, h3, l3);
        int off = r * 256 + ((c ^ (r & 7)) << 4);
        *(uint4*)(sm + offH + off) = make_uint4(h0, h1, h2, h3);
        *(uint4*)(sm + offL + off) = make_uint4(l0, l1, l2, l3);
    }
}

// ---------------------------------------------------------------------------
// K0: embedding gather + Fp = (l+1) * E @ w ; emits packed pairs only
// ---------------------------------------------------------------------------
__global__ void k_embed(const void* __restrict__ xraw,
                        const float* __restrict__ ae,
                        const float* __restrict__ w)
{
    __shared__ float sW[ND][ND];
    __shared__ float sE[4][ND];

    int tid = threadIdx.x;

    // Detect index dtype: int64 (odd 32-bit words all zero) vs int32.
    const int* xi = (const int*)xraw;
    int oddw = xi[((tid & 63) << 1) + 1];
    int is64 = __syncthreads_and(oddw == 0);

    for (int i = tid; i < ND * ND; i += 256)
        ((float*)sW)[i] = w[i];

    int q = tid >> 6;
    int d = tid & 63;
    int t = blockIdx.x * 4 + q;
    int l = t & (NL - 1);

    long long v;
    if (is64) v = ((const long long*)xraw)[t];
    else      v = (long long)xi[t];

    float e = ae[v * ND + d];
    sE[q][d] = e;
    size_t td = (size_t)t * ND + d;
    cEp[td] = packsplit(e);
    __syncthreads();

    float acc = 0.f;
    #pragma unroll
    for (int k = 0; k < ND; k++)
        acc += sE[q][k] * sW[k][d];

    cFp[td] = packsplit((float)(l + 1) * acc);
}

// ---------------------------------------------------------------------------
// K1b: intra-chunk scores S[j][i] = E[j].Fp[i], zero for i >= j (scalar fp32)
// reconstructs E/Fp from packed; emits packed masked S.
// ---------------------------------------------------------------------------
__global__ void k_scores()
{
    __shared__ float sEt[32][CK];
    __shared__ float sFt[32][CK];

    int tid = threadIdx.x;
    int c = blockIdx.x, b = blockIdx.y;

    const u32* Eb  = cEp + ((size_t)b * NL + c * CK) * ND;
    const u32* Fpb = cFp + ((size_t)b * NL + c * CK) * ND;

    int tj = tid & 15;
    int ti = tid >> 4;

    float acc[8][8];
    #pragma unroll
    for (int r = 0; r < 8; r++)
        #pragma unroll
        for (int s = 0; s < 8; s++) acc[r][s] = 0.f;

    for (int dt = 0; dt < ND; dt += 32) {
        int f4 = tid & 7, r0 = tid >> 3;
        #pragma unroll
        for (int rep = 0; rep < 4; rep++) {
            int row = r0 + rep * 32;
            uint4 v = *(const uint4*)(Eb + (size_t)row * ND + dt + f4 * 4);
            sEt[f4*4+0][row] = rec(v.x); sEt[f4*4+1][row] = rec(v.y);
            sEt[f4*4+2][row] = rec(v.z); sEt[f4*4+3][row] = rec(v.w);
            uint4 u = *(const uint4*)(Fpb + (size_t)row * ND + dt + f4 * 4);
            sFt[f4*4+0][row] = rec(u.x); sFt[f4*4+1][row] = rec(u.y);
            sFt[f4*4+2][row] = rec(u.z); sFt[f4*4+3][row] = rec(u.w);
        }
        __syncthreads();

        #pragma unroll 8
        for (int kk = 0; kk < 32; kk++) {
            float4 a0 = *(const float4*)&sEt[kk][tj*8];
            float4 a1 = *(const float4*)&sEt[kk][tj*8 + 4];
            float4 b0 = *(const float4*)&sFt[kk][ti*8];
            float4 b1 = *(const float4*)&sFt[kk][ti*8 + 4];
            float av[8] = {a0.x,a0.y,a0.z,a0.w,a1.x,a1.y,a1.z,a1.w};
            float bv[8] = {b0.x,b0.y,b0.z,b0.w,b1.x,b1.y,b1.z,b1.w};
            #pragma unroll
            for (int r = 0; r < 8; r++)
                #pragma unroll
                for (int s = 0; s < 8; s++)
                    acc[r][s] += av[r] * bv[s];
        }
        __syncthreads();
    }

    u32* Sout = cSp + (size_t)(b * NCH + c) * CK * CK;
    #pragma unroll
    for (int r = 0; r < 8; r++) {
        int j = tj * 8 + r;
        u32* row = Sout + (size_t)j * CK + ti * 8;
        u32 pk[8];
        #pragma unroll
        for (int s = 0; s < 8; s++)
            pk[s] = (ti * 8 + s < j) ? packsplit(acc[r][s]) : 0u;
        *(uint4*)row       = make_uint4(pk[0], pk[1], pk[2], pk[3]);
        *(uint4*)(row + 4) = make_uint4(pk[4], pk[5], pk[6], pk[7]);
    }
}

// ---------------------------------------------------------------------------
// K1a (mma): M[b][c][d][h] = sum_i Fp[i][d] * X[i][h]  (fp32 out)
// A = Fp (packed, deinterleave), B = X (convert). CTA 64x128, warps 2x4.
// ---------------------------------------------------------------------------
#define KO_AH 0
#define KO_AL 8192
#define KO_BH 16384
#define KO_BL 32768
#define KO_TOT 49152

__global__ void __launch_bounds__(256, 1) k_outer_mma(const float* __restrict__ bx)
{
    extern __shared__ char sm[];
    u32 smb = smem_u32(sm);
    int tid = threadIdx.x, wid = tid >> 5, ln = tid & 31;
    int ht = blockIdx.x, c = blockIdx.y, b = blockIdx.z;
    int h0 = ht * HT;
    int mw = (wid >> 2) * 32;
    int nw = (wid & 3) * 32;

    const u32* Fg = cFp + ((size_t)b * NL + c * CK) * ND;
    const float* Xg = bx + ((size_t)b * NL + c * CK) * NH + h0;

    float acc[2][4][4];
    #pragma unroll
    for (int i = 0; i < 2; i++)
        #pragma unroll
        for (int j = 0; j < 4; j++)
            #pragma unroll
            for (int k = 0; k < 4; k++) acc[i][j][k] = 0.f;

    for (int slab = 0; slab < 2; slab++) {
        loadAdi<64>(sm, KO_AH, KO_AL, Fg + (size_t)slab * 64 * ND, ND, tid);
        loadBcv(sm, KO_BH, KO_BL, Xg + (size_t)slab * 64 * NH, NH, tid);
        __syncthreads();

        #pragma unroll
        for (int ks = 0; ks < 4; ks++) {
            u32 ah[2][4], al[2][4], bh[2][4], bl[2][4];
            int q = ln >> 3;
            #pragma unroll
            for (int mt = 0; mt < 2; mt++) {   // A trans: rows=k(i), cols=m(d)
                int r = ks * 16 + (q >> 1) * 8 + (ln & 7);
                int mc = (mw + mt * 16 + (q & 1) * 8) >> 3;
                u32 off = r * 128 + ((mc ^ (r & 7)) << 4);
                ldsm4t(ah[mt], smb + KO_AH + off);
                ldsm4t(al[mt], smb + KO_AL + off);
            }
            #pragma unroll
            for (int nt2 = 0; nt2 < 2; nt2++) { // B trans: rows=k(i), cols=n(h)
                int r = ks * 16 + (q & 1) * 8 + (ln & 7);
                int nc = (nw + nt2 * 16 + (q >> 1) * 8) >> 3;
                u32 off = r * 256 + ((nc ^ (r & 7)) << 4);
                ldsm4t(bh[nt2], smb + KO_BH + off);
                ldsm4t(bl[nt2], smb + KO_BL + off);
            }
            #pragma unroll
            for (int mt = 0; mt < 2; mt++)
                #pragma unroll
                for (int nt2 = 0; nt2 < 2; nt2++) {
                    mma16816(acc[mt][nt2*2],   ah[mt], &bh[nt2][0]);
                    mma16816(acc[mt][nt2*2+1], ah[mt], &bh[nt2][2]);
                    mma16816(acc[mt][nt2*2],   ah[mt], &bl[nt2][0]);
                    mma16816(acc[mt][nt2*2+1], ah[mt], &bl[nt2][2]);
                    mma16816(acc[mt][nt2*2],   al[mt], &bh[nt2][0]);
                    mma16816(acc[mt][nt2*2+1], al[mt], &bh[nt2][2]);
                }
        }
        __syncthreads();
    }

    float* Mo = g_M + (size_t)(b * NCH + c) * DH;
    #pragma unroll
    for (int mt = 0; mt < 2; mt++)
        #pragma unroll
        for (int half = 0; half < 2; half++) {
            int d = mw + mt * 16 + (ln >> 2) + half * 8;
            #pragma unroll
            for (int nt = 0; nt < 4; nt++) {
                int h = h0 + nw + nt * 8 + (ln & 3) * 2;
                *(float2*)(Mo + (size_t)d * NH + h) =
                    make_float2(acc[mt][nt][half*2], acc[mt][nt][half*2 + 1]);
            }
        }
}

// ---------------------------------------------------------------------------
// K2: exclusive prefix over chunks; converts g_M fp32 -> packed IN PLACE.
// ---------------------------------------------------------------------------
__global__ void k_prefix()
{
    int idx = blockIdx.x * 256 + threadIdx.x;      // < NB*DH/4
    int b = idx / (DH / 4);
    int q = idx - b * (DH / 4);
    size_t p = (size_t)(b * NCH) * DH + (size_t)q * 4;
    float4 run = make_float4(0.f, 0.f, 0.f, 0.f);
    #pragma unroll
    for (int c = 0; c < NCH; c++) {
        float4 v = *(const float4*)&g_M[p];
        *(uint4*)&g_M[p] = make_uint4(packsplit(run.x), packsplit(run.y),
                                      packsplit(run.z), packsplit(run.w));
        run.x += v.x; run.y += v.y; run.z += v.z; run.w += v.w;
        p += DH;
    }
}

// ---------------------------------------------------------------------------
// K3 (mma): out[j][h] = X[j][h] + (1/(j+1)) * ( E@M + tril(S,-1)@X )
// slab0: A=E(packed), B=M(packed); slab1,2: A=S(packed), B=X(convert).
// CTA 128x128, warps 2x4, warp tile 64x32.
// ---------------------------------------------------------------------------
#define KF_AH 0
#define KF_AL 16384
#define KF_BH 32768
#define KF_BL 49152
#define KF_TOT 65536

__global__ void __launch_bounds__(256, 1) k_final_mma(const float* __restrict__ bx,
                                                      float* __restrict__ out)
{
    extern __shared__ char sm[];
    u32 smb = smem_u32(sm);
    int tid = threadIdx.x, wid = tid >> 5, ln = tid & 31;
    int ht = blockIdx.x, c = blockIdx.y, b = blockIdx.z;
    int h0 = ht * HT;
    int mw = (wid >> 2) * 64;
    int nw = (wid & 3) * 32;

    const u32* Eg = cEp + ((size_t)b * NL + c * CK) * ND;
    const u32* Sg = cSp + (size_t)(b * NCH + c) * CK * CK;
    const u32* Mg = (const u32*)g_M + (size_t)(b * NCH + c) * DH + h0;
    const float* Xg = bx + ((size_t)b * NL + c * CK) * NH + h0;

    float acc[4][4][4];
    #pragma unroll
    for (int i = 0; i < 4; i++)
        #pragma unroll
        for (int j = 0; j < 4; j++)
            #pragma unroll
            for (int k = 0; k < 4; k++) acc[i][j][k] = 0.f;

    for (int slab = 0; slab < 3; slab++) {
        if (slab == 0) {
            loadAdi<128>(sm, KF_AH, KF_AL, Eg, ND, tid);
            loadBdi(sm, KF_BH, KF_BL, Mg, NH, tid);
        } else {
            loadAdi<128>(sm, KF_AH, KF_AL, Sg + (size_t)(slab - 1) * 64, CK, tid);
            loadBcv(sm, KF_BH, KF_BL, Xg + (size_t)(slab - 1) * 64 * NH, NH, tid);
        }
        __syncthreads();

        #pragma unroll
        for (int ks = 0; ks < 4; ks++) {
            u32 ah[4][4], al[4][4], bh[2][4], bl[2][4];
            #pragma unroll
            for (int mt = 0; mt < 4; mt++) {   // A non-trans: rows=m(j), cols=k
                int row = mw + mt * 16 + (ln & 15);
                int kc = ks * 2 + (ln >> 4);
                u32 off = row * 128 + ((kc ^ (row & 7)) << 4);
                ldsm4(ah[mt], smb + KF_AH + off);
                ldsm4(al[mt], smb + KF_AL + off);
            }
            int q = ln >> 3;
            #pragma unroll
            for (int nt2 = 0; nt2 < 2; nt2++) { // B trans: rows=k, cols=n(h)
                int r = ks * 16 + (q & 1) * 8 + (ln & 7);
                int nc = (nw + nt2 * 16 + (q >> 1) * 8) >> 3;
                u32 off = r * 256 + ((nc ^ (r & 7)) << 4);
                ldsm4t(bh[nt2], smb + KF_BH + off);
                ldsm4t(bl[nt2], smb + KF_BL + off);
            }
            #pragma unroll
            for (int mt = 0; mt < 4; mt++)
                #pragma unroll
                for (int nt2 = 0; nt2 < 2; nt2++) {
                    mma16816(acc[mt][nt2*2],   ah[mt], &bh[nt2][0]);
                    mma16816(acc[mt][nt2*2+1], ah[mt], &bh[nt2][2]);
                    mma16816(acc[mt][nt2*2],   ah[mt], &bl[nt2][0]);
                    mma16816(acc[mt][nt2*2+1], ah[mt], &bl[nt2][2]);
                    mma16816(acc[mt][nt2*2],   al[mt], &bh[nt2][0]);
                    mma16816(acc[mt][nt2*2+1], al[mt], &bh[nt2][2]);
                }
        }
        __syncthreads();
    }

    // Epilogue: out = x + (1/(j+1)) * acc
    #pragma unroll
    for (int mt = 0; mt < 4; mt++)
        #pragma unroll
        for (int half = 0; half < 2; half++) {
            int jl = mw + mt * 16 + (ln >> 2) + half * 8;
            float rj = 1.f / (float)(c * CK + jl + 1);
            size_t base = ((size_t)b * NL + c * CK + jl) * NH + h0 + nw + (ln & 3) * 2;
            #pragma unroll
            for (int nt = 0; nt < 4; nt++) {
                float2 x = *(const float2*)(bx + base + nt * 8);
                *(float2*)(out + base + nt * 8) =
                    make_float2(x.x + rj * acc[mt][nt][half*2],
                                x.y + rj * acc[mt][nt][half*2 + 1]);
            }
        }
}

// ---------------------------------------------------------------------------
extern "C" void kernel_launch(void* const* d_in, const int* in_sizes, int n_in,
                              void* d_out, int out_size)
{
    const float* bx = (const float*)d_in[0];   // bert_x [B,L,H] f32
    const void*  x  = d_in[1];                 // x      [B,L]   int32/int64 (auto)
    const float* ae = (const float*)d_in[2];   // ae     [V,D]   f32
    const float* w  = (const float*)d_in[3];   // w      [D,D]   f32
    float* out = (float*)d_out;

    (void)in_sizes; (void)n_in; (void)out_size;

    cudaFuncSetAttribute(k_outer_mma, cudaFuncAttributeMaxDynamicSharedMemorySize, KO_TOT);
    cudaFuncSetAttribute(k_final_mma, cudaFuncAttributeMaxDynamicSharedMemorySize, KF_TOT);

    k_embed    <<<NB * NL / 4, 256>>>(x, ae, w);
    k_scores   <<<dim3(NCH, NB), 256>>>();
    k_outer_mma<<<dim3(NHT, NCH, NB), 256, KO_TOT>>>(bx);
    k_prefix   <<<NB * DH / 1024, 256>>>();
    k_final_mma<<<dim3(NHT, NCH, NB), 256, KF_TOT>>>(bx, out);
}